// round 7
// baseline (speedup 1.0000x reference)
#include <cuda_runtime.h>
#include <cuda_bf16.h>

#define NN   4096
#define TT   48
#define HH   64
#define C4   256
#define MAXW 128
#define ROWS 28
#define NTHR 448
#define GRID 147

typedef unsigned long long ull;

// ---------------- device scratch (no allocations allowed) ----------------
__device__ __align__(16) float g_dinv[NN];
__device__ __align__(16) int2  g_cv[NN * MAXW];    // (col, __float_as_int(val))
__device__ __align__(16) int   g_len[NN];
__device__ __align__(16) float g_AX[TT * NN * 2];
__device__ __align__(16) float g_W0[128 * C4];     // [gcWh0 ; liWh0]
__device__ __align__(16) float g_Wx0[4 * C4];      // [gcWi0 ; liWi0]
__device__ __align__(16) float g_b0[C4];
__device__ __align__(16) float g_W1[256 * C4];     // [gcWi1 ; liWi1 ; gcWh1 ; liWh1]
__device__ __align__(16) float g_b1[C4];
__device__ __align__(16) __nv_bfloat16 g_bh0[2][NN * HH];  // bf16 mirrors of h (gather source)
__device__ __align__(16) __nv_bfloat16 g_bh1[2][NN * HH];
__device__ unsigned g_count = 0;
__device__ volatile unsigned g_gen = 0;

// ---------------- helpers ----------------
__device__ __forceinline__ ull pack2(float x, float y) {
    ull r; asm("mov.b64 %0,{%1,%2};" : "=l"(r) : "f"(x), "f"(y)); return r;
}
__device__ __forceinline__ void unpack2(ull v, float& x, float& y) {
    asm("mov.b64 {%0,%1},%2;" : "=f"(x), "=f"(y) : "l"(v));
}
// Blackwell packed dual-FMA (2x fp32 throughput); PTX-only form
__device__ __forceinline__ void fma2(ull& d, ull a, ull b) {
    asm("fma.rn.f32x2 %0,%1,%2,%0;" : "+l"(d) : "l"(a), "l"(b));
}
__device__ __forceinline__ float sigf(float v)  { return 1.f / (1.f + __expf(-v)); }
__device__ __forceinline__ float tanhf2(float v){ return 2.f / (1.f + __expf(-2.f * v)) - 1.f; }

// Grid-wide sense-reversing barrier. All 147 blocks are guaranteed co-resident
// (1 block/SM by smem, 147 <= 148 SMs). Last barrier resets generation to 0 so
// consecutive graph replays start clean.
__device__ __forceinline__ void gsync(unsigned& mygen, bool reset) {
    __syncthreads();
    if (threadIdx.x == 0) {
        __threadfence();
        unsigned a = atomicAdd(&g_count, 1u);
        if (a == GRID - 1) {
            g_count = 0;
            __threadfence();
            g_gen = reset ? 0u : (mygen + 1u);
        } else {
            while (g_gen == mygen) __nanosleep(64);
        }
        __threadfence();
    }
    __syncthreads();
    mygen = reset ? 0u : (mygen + 1u);
}

// ---------------- setup kernels ----------------
__global__ void k_dinv(const float* __restrict__ adj) {
    int row  = blockIdx.x * 8 + (threadIdx.x >> 5);
    int lane = threadIdx.x & 31;
    if (row >= NN) return;
    float s = 0.f;
    for (int j = lane; j < NN; j += 32) s += adj[(size_t)row * NN + j];
    #pragma unroll
    for (int o = 16; o; o >>= 1) s += __shfl_xor_sync(0xffffffffu, s, o);
    if (lane == 0) g_dinv[row] = rsqrtf(s + 1.f);   // A = adj + I
}

__global__ void k_build(const float* __restrict__ adj) {
    int row  = blockIdx.x * 8 + (threadIdx.x >> 5);
    int lane = threadIdx.x & 31;
    if (row >= NN) return;
    float dr = g_dinv[row];
    int base = 0;
    for (int j0 = 0; j0 < NN; j0 += 32) {
        int   j    = j0 + lane;
        float v    = adj[(size_t)row * NN + j];
        bool  pres = (v != 0.f) || (j == row);
        float aval = v + ((j == row) ? 1.f : 0.f);
        unsigned m = __ballot_sync(0xffffffffu, pres);
        if (pres) {
            int pos = base + __popc(m & ((1u << lane) - 1u));
            if (pos < MAXW)
                g_cv[row * MAXW + pos] = make_int2(j, __float_as_int(aval * dr * g_dinv[j]));
        }
        base += __popc(m);
    }
    if (base > MAXW) base = MAXW;
    if (lane == 0) g_len[row] = base;
}

// weight packing + A@x precompute, one kernel
__global__ void k_prep(const float* __restrict__ x,
                       const float* gcWi0, const float* gcWh0, const float* liWi0, const float* liWh0,
                       const float* gcWi1, const float* liWi1, const float* gcWh1, const float* liWh1,
                       const float* bi0, const float* bh0, const float* lbi0, const float* lbh0,
                       const float* bi1, const float* bh1, const float* lbi1, const float* lbh1) {
    int idx = blockIdx.x * blockDim.x + threadIdx.x;
    const int W0E = 128 * C4, W1E = 256 * C4, WXE = 4 * C4;
    if (idx < W0E) {
        int r = idx >> 8, c = idx & 255;
        g_W0[idx] = (r < 64) ? gcWh0[r * C4 + c] : liWh0[(r - 64) * C4 + c];
    } else if (idx < W0E + W1E) {
        int j = idx - W0E; int r = j >> 8, c = j & 255;
        int seg = r >> 6, rr = r & 63;
        const float* s = (seg == 0) ? gcWi1 : (seg == 1) ? liWi1 : (seg == 2) ? gcWh1 : liWh1;
        g_W1[j] = s[rr * C4 + c];
    } else if (idx < W0E + W1E + WXE) {
        int j = idx - W0E - W1E; int q = j >> 8, c = j & 255;
        g_Wx0[j] = (q < 2) ? gcWi0[q * C4 + c] : liWi0[(q - 2) * C4 + c];
    } else if (idx < W0E + W1E + WXE + C4) {
        int c = idx - (W0E + W1E + WXE);
        g_b0[c] = bi0[c] + bh0[c] + lbi0[c] + lbh0[c];
    } else if (idx < W0E + W1E + WXE + 2 * C4) {
        int c = idx - (W0E + W1E + WXE + C4);
        g_b1[c] = bi1[c] + bh1[c] + lbi1[c] + lbh1[c];
    }
    // A @ x for all timesteps
    if (idx < TT * NN) {
        int t = idx / NN, i = idx - t * NN;
        int len = g_len[i];
        const int2* cp = g_cv + (size_t)i * MAXW;
        float a0 = 0.f, a1 = 0.f;
        for (int k = 0; k < len; k++) {
            int2 cv = cp[k];
            float v = __int_as_float(cv.y);
            float2 xv = *(const float2*)&x[(size_t)t * (NN * 2) + cv.x * 2];
            a0 += v * xv.x; a1 += v * xv.y;
        }
        *(float2*)&g_AX[((size_t)t * NN + i) * 2] = make_float2(a0, a1);
    }
}

// ================= persistent main kernel: all 48 steps + output =================
// dyn smem (floats):
//   suA0[28*64] | suA1[28*64] | hl0[28*64] | hl1[28*64] | sW[2][16][256] (=comb) | sWx[4*256] | sx[28*4]
#define S_A0 0
#define S_A1 (S_A0 + ROWS * 64)
#define S_H0 (S_A1 + ROWS * 64)
#define S_H1 (S_H0 + ROWS * 64)
#define S_W  (S_H1 + ROWS * 64)
#define S_WX (S_W + 2 * 16 * C4)
#define S_SX (S_WX + 4 * C4)
#define SMEMF (S_SX + ROWS * 4)
#define SMEMB (SMEMF * 4)

// gather 4 bf16 (8 B = one L2 line per row-group of 16 lanes)
__device__ __forceinline__ void gacc(float4& a, float v, const __nv_bfloat16* bh, int c, int lane) {
    uint2 raw = __ldcg((const uint2*)(bh + (size_t)c * HH) + lane);
    __nv_bfloat162 b01 = *(__nv_bfloat162*)&raw.x;
    __nv_bfloat162 b23 = *(__nv_bfloat162*)&raw.y;
    float2 f01 = __bfloat1622float2(b01), f23 = __bfloat1622float2(b23);
    a.x += v * f01.x; a.y += v * f01.y; a.z += v * f23.x; a.w += v * f23.y;
}

__global__ __launch_bounds__(NTHR, 1) void k_main(const float* __restrict__ x,
                                                  const float* __restrict__ outW,
                                                  const float* __restrict__ outb,
                                                  float* __restrict__ out) {
    extern __shared__ __align__(16) float sm[];
    float* suA0 = sm + S_A0;
    float* suA1 = sm + S_A1;
    float* hl0  = sm + S_H0;
    float* hl1  = sm + S_H1;
    float (*sW)[16][C4] = (float(*)[16][C4])(sm + S_W);
    float* cw   = sm + S_W;                 // comb aliases sW
    float (*sWx)[C4] = (float(*)[C4])(sm + S_WX);
    float (*sx)[4]   = (float(*)[4])(sm + S_SX);

    const int tid  = threadIdx.x;
    const int row0 = blockIdx.x * ROWS;
    unsigned gen = 0;

    // thread-owned gate slots: i = tid + it*NTHR -> (r = i>>6, h = i&63); c-state in regs
    float c0l[4] = {0.f, 0.f, 0.f, 0.f};
    float c1l[4] = {0.f, 0.f, 0.f, 0.f};

    // init: local h zero, publish zero bf16 mirrors (buffer 0), stage sWx
    #pragma unroll
    for (int it = 0; it < 4; it++) {
        int i = tid + it * NTHR;
        hl0[i] = 0.f; hl1[i] = 0.f;
        int grow = row0 + (i >> 6), h = i & 63;
        if (grow < NN) {
            g_bh0[0][(size_t)grow * HH + h] = __float2bfloat16(0.f);
            g_bh1[0][(size_t)grow * HH + h] = __float2bfloat16(0.f);
        }
    }
    if (tid < 256) {
        int kk = tid >> 6, q = tid & 63;
        *(float4*)&sWx[kk][q * 4] = *(const float4*)&g_Wx0[kk * C4 + q * 4];
    }
    gsync(gen, false);

    const int cg = tid & 63, rg = tid >> 6;      // rg 0..6
    const int c0 = cg * 4, r0 = rg * 4;
    const int grow_g = min(row0 + (tid >> 4), NN - 1);   // gather row for this thread
    const int lane_g = tid & 15;
    const int len_g  = g_len[grow_g];
    const int2* cvb  = g_cv + (size_t)grow_g * MAXW;

    for (int t = 0; t < TT; t++) {
        const int pin = t & 1, pout = pin ^ 1;
        // ======================= phase A (cell 0) =======================
        {
            const __nv_bfloat16* bin = g_bh0[pin];
            if (tid < ROWS) {
                int grow = min(row0 + tid, NN - 1);
                float2 axv = *(const float2*)&g_AX[((size_t)t * NN + grow) * 2];
                float2 xv  = *(const float2*)&x[(size_t)t * (NN * 2) + grow * 2];
                sx[tid][0] = axv.x; sx[tid][1] = axv.y;
                sx[tid][2] = xv.x;  sx[tid][3] = xv.y;
            }
            const float4* W4 = (const float4*)g_W0;
            float4 pf0 = W4[tid], pf1 = W4[tid + 448], pf2;
            if (tid < 128) pf2 = W4[tid + 896];
            // gather A @ h0_old (bf16) -> suA0
            {
                float4 a4 = make_float4(0.f, 0.f, 0.f, 0.f);
                #pragma unroll 2
                for (int k = 0; k < len_g; k++) {
                    int2 cv = __ldg(&cvb[k]);
                    gacc(a4, __int_as_float(cv.y), bin, cv.x, lane_g);
                }
                *(float4*)&suA0[(tid >> 4) * 64 + lane_g * 4] = a4;
            }
            {
                float4* s4 = (float4*)sW[0];
                s4[tid] = pf0; s4[tid + 448] = pf1; if (tid < 128) s4[tid + 896] = pf2;
            }
            __syncthreads();

            // GEMM [28x128]@[128x256] + x-term
            ull acc[4][2];
            {
                float4 bb = *(const float4*)&g_b0[c0];
                ull b01 = pack2(bb.x, bb.y), b23 = pack2(bb.z, bb.w);
                #pragma unroll
                for (int r = 0; r < 4; r++) { acc[r][0] = b01; acc[r][1] = b23; }
                #pragma unroll
                for (int q = 0; q < 4; q++) {
                    float4 wv = *(const float4*)&sWx[q][c0];
                    ull w01 = pack2(wv.x, wv.y), w23 = pack2(wv.z, wv.w);
                    #pragma unroll
                    for (int r = 0; r < 4; r++) {
                        float uv = sx[r0 + r][q];
                        ull uu = pack2(uv, uv);
                        fma2(acc[r][0], uu, w01); fma2(acc[r][1], uu, w23);
                    }
                }
            }
            #pragma unroll 1
            for (int kt = 0; kt < 8; kt++) {
                float4 pa, pb, pc;
                if (kt < 7) {
                    const float4* Wn = W4 + (size_t)(kt + 1) * 1024;
                    pa = Wn[tid]; pb = Wn[tid + 448]; if (tid < 128) pc = Wn[tid + 896];
                }
                const float (*sWb)[C4] = sW[kt & 1];
                const float* ub = ((kt >> 2) ? hl0 : suA0) + (kt & 3) * 16;
                #pragma unroll
                for (int kk = 0; kk < 16; kk += 2) {
                    float4 wa = *(const float4*)&sWb[kk][c0];
                    float4 wb = *(const float4*)&sWb[kk + 1][c0];
                    ull wa01 = pack2(wa.x, wa.y), wa23 = pack2(wa.z, wa.w);
                    ull wb01 = pack2(wb.x, wb.y), wb23 = pack2(wb.z, wb.w);
                    #pragma unroll
                    for (int r = 0; r < 4; r++) {
                        float2 uv = *(const float2*)&ub[(r0 + r) * 64 + kk];
                        ull u0 = pack2(uv.x, uv.x), u1 = pack2(uv.y, uv.y);
                        fma2(acc[r][0], u0, wa01); fma2(acc[r][1], u0, wa23);
                        fma2(acc[r][0], u1, wb01); fma2(acc[r][1], u1, wb23);
                    }
                }
                __syncthreads();
                if (kt < 7) {
                    float4* s4 = (float4*)sW[(kt + 1) & 1];
                    s4[tid] = pa; s4[tid + 448] = pb; if (tid < 128) s4[tid + 896] = pc;
                    __syncthreads();
                }
            }
            // comb -> gates -> update local h0/c0 + publish bf16
            #pragma unroll
            for (int r = 0; r < 4; r++) {
                float a, b;
                unpack2(acc[r][0], a, b); *(float2*)&cw[(r0 + r) * C4 + c0]     = make_float2(a, b);
                unpack2(acc[r][1], a, b); *(float2*)&cw[(r0 + r) * C4 + c0 + 2] = make_float2(a, b);
            }
            __syncthreads();
            __nv_bfloat16* bo = g_bh0[pout];
            #pragma unroll
            for (int it = 0; it < 4; it++) {
                int i = tid + it * NTHR;
                int r = i >> 6, h = i & 63;
                float ig = cw[r * C4 + h],       fg = cw[r * C4 + 64 + h];
                float og = cw[r * C4 + 128 + h], gg = cw[r * C4 + 192 + h];
                float cv = sigf(fg) * c0l[it] + sigf(ig) * tanhf2(gg);
                c0l[it] = cv;
                float hv = sigf(og) * tanhf2(cv);
                hl0[i] = hv;
                int grow = row0 + r;
                if (grow < NN) bo[(size_t)grow * HH + h] = __float2bfloat16(hv);
            }
        }
        gsync(gen, false);
        // ======================= phase B (cell 1) =======================
        {
            const __nv_bfloat16* bin0 = g_bh0[pout];   // new h0
            const __nv_bfloat16* bin1 = g_bh1[pin];    // old h1
            const float4* W4 = (const float4*)g_W1;
            float4 pf0 = W4[tid], pf1 = W4[tid + 448], pf2;
            if (tid < 128) pf2 = W4[tid + 896];
            {
                float4 a0 = make_float4(0.f, 0.f, 0.f, 0.f);
                float4 a1 = make_float4(0.f, 0.f, 0.f, 0.f);
                #pragma unroll 2
                for (int k = 0; k < len_g; k++) {
                    int2 cv = __ldg(&cvb[k]);
                    float v = __int_as_float(cv.y);
                    gacc(a0, v, bin0, cv.x, lane_g);
                    gacc(a1, v, bin1, cv.x, lane_g);
                }
                *(float4*)&suA0[(tid >> 4) * 64 + lane_g * 4] = a0;
                *(float4*)&suA1[(tid >> 4) * 64 + lane_g * 4] = a1;
            }
            {
                float4* s4 = (float4*)sW[0];
                s4[tid] = pf0; s4[tid + 448] = pf1; if (tid < 128) s4[tid + 896] = pf2;
            }
            __syncthreads();

            ull acc[4][2];
            {
                float4 bb = *(const float4*)&g_b1[c0];
                ull b01 = pack2(bb.x, bb.y), b23 = pack2(bb.z, bb.w);
                #pragma unroll
                for (int r = 0; r < 4; r++) { acc[r][0] = b01; acc[r][1] = b23; }
            }
            #pragma unroll 1
            for (int kt = 0; kt < 16; kt++) {
                float4 pa, pb, pc;
                if (kt < 15) {
                    const float4* Wn = W4 + (size_t)(kt + 1) * 1024;
                    pa = Wn[tid]; pb = Wn[tid + 448]; if (tid < 128) pc = Wn[tid + 896];
                }
                const float (*sWb)[C4] = sW[kt & 1];
                const int seg = kt >> 2;
                const float* ub = ((seg == 0) ? suA0 : (seg == 1) ? hl0 : (seg == 2) ? suA1 : hl1)
                                  + (kt & 3) * 16;
                #pragma unroll
                for (int kk = 0; kk < 16; kk += 2) {
                    float4 wa = *(const float4*)&sWb[kk][c0];
                    float4 wb = *(const float4*)&sWb[kk + 1][c0];
                    ull wa01 = pack2(wa.x, wa.y), wa23 = pack2(wa.z, wa.w);
                    ull wb01 = pack2(wb.x, wb.y), wb23 = pack2(wb.z, wb.w);
                    #pragma unroll
                    for (int r = 0; r < 4; r++) {
                        float2 uv = *(const float2*)&ub[(r0 + r) * 64 + kk];
                        ull u0 = pack2(uv.x, uv.x), u1 = pack2(uv.y, uv.y);
                        fma2(acc[r][0], u0, wa01); fma2(acc[r][1], u0, wa23);
                        fma2(acc[r][0], u1, wb01); fma2(acc[r][1], u1, wb23);
                    }
                }
                __syncthreads();
                if (kt < 15) {
                    float4* s4 = (float4*)sW[(kt + 1) & 1];
                    s4[tid] = pa; s4[tid + 448] = pb; if (tid < 128) s4[tid + 896] = pc;
                    __syncthreads();
                }
            }
            #pragma unroll
            for (int r = 0; r < 4; r++) {
                float a, b;
                unpack2(acc[r][0], a, b); *(float2*)&cw[(r0 + r) * C4 + c0]     = make_float2(a, b);
                unpack2(acc[r][1], a, b); *(float2*)&cw[(r0 + r) * C4 + c0 + 2] = make_float2(a, b);
            }
            __syncthreads();
            __nv_bfloat16* bo = g_bh1[pout];
            #pragma unroll
            for (int it = 0; it < 4; it++) {
                int i = tid + it * NTHR;
                int r = i >> 6, h = i & 63;
                float ig = cw[r * C4 + h],       fg = cw[r * C4 + 64 + h];
                float og = cw[r * C4 + 128 + h], gg = cw[r * C4 + 192 + h];
                float cv = sigf(fg) * c1l[it] + sigf(ig) * tanhf2(gg);
                c1l[it] = cv;
                float hv = sigf(og) * tanhf2(cv);
                hl1[i] = hv;
                int grow = row0 + r;
                if (grow < NN) bo[(size_t)grow * HH + h] = __float2bfloat16(hv);
            }
        }
        gsync(gen, t == TT - 1);
    }

    // output projection from block-local fp32 h1
    for (int o = tid; o < ROWS * 12; o += NTHR) {
        int r = o / 12, p = o - r * 12;
        int grow = row0 + r;
        if (grow < NN) {
            float s = outb[p];
            #pragma unroll
            for (int k = 0; k < HH; k++) s += hl1[r * 64 + k] * outW[k * 12 + p];
            out[grow * 12 + p] = s;
        }
    }
}

extern "C" void kernel_launch(void* const* d_in, const int* in_sizes, int n_in,
                              void* d_out, int out_size) {
    const float* x     = (const float*)d_in[0];
    const float* adj   = (const float*)d_in[1];
    const float* gcWi0 = (const float*)d_in[2];
    const float* gcbi0 = (const float*)d_in[3];
    const float* gcWh0 = (const float*)d_in[4];
    const float* gcbh0 = (const float*)d_in[5];
    const float* liWi0 = (const float*)d_in[6];
    const float* libi0 = (const float*)d_in[7];
    const float* liWh0 = (const float*)d_in[8];
    const float* libh0 = (const float*)d_in[9];
    const float* gcWi1 = (const float*)d_in[10];
    const float* gcbi1 = (const float*)d_in[11];
    const float* gcWh1 = (const float*)d_in[12];
    const float* gcbh1 = (const float*)d_in[13];
    const float* liWi1 = (const float*)d_in[14];
    const float* libi1 = (const float*)d_in[15];
    const float* liWh1 = (const float*)d_in[16];
    const float* libh1 = (const float*)d_in[17];
    const float* outW  = (const float*)d_in[18];
    const float* outb  = (const float*)d_in[19];
    float* out = (float*)d_out;

    cudaFuncSetAttribute(k_main, cudaFuncAttributeMaxDynamicSharedMemorySize, SMEMB);

    k_dinv<<<NN / 8, 256>>>(adj);
    k_build<<<NN / 8, 256>>>(adj);
    k_prep<<<(TT * NN + 255) / 256, 256>>>(x,
        gcWi0, gcWh0, liWi0, liWh0, gcWi1, liWi1, gcWh1, liWh1,
        gcbi0, gcbh0, libi0, libh0, gcbi1, gcbh1, libi1, libh1);
    k_main<<<GRID, NTHR, SMEMB>>>(x, outW, outb, out);
}

// round 11
// speedup vs baseline: 1.1400x; 1.1400x over previous
#include <cuda_runtime.h>
#include <cuda_bf16.h>

#define NN   4096
#define TT   48
#define HH   64
#define C4   256
#define MAXW 128
#define ROWS 28
#define NTHR 448
#define GRID 147

typedef unsigned long long ull;

// ---------------- device scratch (no allocations allowed) ----------------
__device__ __align__(16) float g_dinv[NN];
__device__ __align__(16) int2  g_cv[NN * MAXW];    // (col, __float_as_int(val))
__device__ __align__(16) int   g_len[NN];
__device__ __align__(16) float g_AX[TT * NN * 2];
__device__ __align__(16) float g_W0[128 * C4];     // [gcWh0 ; liWh0]
__device__ __align__(16) float g_Wx0[4 * C4];      // [gcWi0 ; liWi0]
__device__ __align__(16) float g_b0[C4];
__device__ __align__(16) float g_W1[256 * C4];     // [gcWi1 ; liWi1 ; gcWh1 ; liWh1]
__device__ __align__(16) float g_b1[C4];
__device__ __align__(16) float g_h0[2][NN * HH];
__device__ __align__(16) float g_c0[2][NN * HH];
__device__ __align__(16) float g_h1[2][NN * HH];
__device__ __align__(16) float g_c1[2][NN * HH];
__device__ __align__(16) __nv_bfloat16 g_bh0[2][NN * HH];  // bf16 mirrors (gather source)
__device__ __align__(16) __nv_bfloat16 g_bh1[2][NN * HH];

// ---------------- helpers ----------------
__device__ __forceinline__ ull pack2(float x, float y) {
    ull r; asm("mov.b64 %0,{%1,%2};" : "=l"(r) : "f"(x), "f"(y)); return r;
}
__device__ __forceinline__ void unpack2(ull v, float& x, float& y) {
    asm("mov.b64 {%0,%1},%2;" : "=f"(x), "=f"(y) : "l"(v));
}
// Blackwell packed dual-FMA (2x fp32 throughput); PTX-only form
__device__ __forceinline__ void fma2(ull& d, ull a, ull b) {
    asm("fma.rn.f32x2 %0,%1,%2,%0;" : "+l"(d) : "l"(a), "l"(b));
}
__device__ __forceinline__ float sigf(float v)  { return 1.f / (1.f + __expf(-v)); }
__device__ __forceinline__ float tanhf2(float v){ return 2.f / (1.f + __expf(-2.f * v)) - 1.f; }

// gather 4 bf16 (8 B = one L2 sector per 16-lane row group)
__device__ __forceinline__ void gacc(float4& a, float v, const __nv_bfloat16* bh, int c, int lane) {
    uint2 raw = *((const uint2*)(bh + (size_t)c * HH) + lane);
    __nv_bfloat162 b01 = *(__nv_bfloat162*)&raw.x;
    __nv_bfloat162 b23 = *(__nv_bfloat162*)&raw.y;
    float2 f01 = __bfloat1622float2(b01), f23 = __bfloat1622float2(b23);
    a.x += v * f01.x; a.y += v * f01.y; a.z += v * f23.x; a.w += v * f23.y;
}

// ---------------- setup kernels ----------------
__global__ void k_dinv(const float* __restrict__ adj) {
    int row  = blockIdx.x * 8 + (threadIdx.x >> 5);
    int lane = threadIdx.x & 31;
    if (row >= NN) return;
    float s = 0.f;
    for (int j = lane; j < NN; j += 32) s += adj[(size_t)row * NN + j];
    #pragma unroll
    for (int o = 16; o; o >>= 1) s += __shfl_xor_sync(0xffffffffu, s, o);
    if (lane == 0) g_dinv[row] = rsqrtf(s + 1.f);   // A = adj + I
}

__global__ void k_build(const float* __restrict__ adj) {
    int row  = blockIdx.x * 8 + (threadIdx.x >> 5);
    int lane = threadIdx.x & 31;
    if (row >= NN) return;
    float dr = g_dinv[row];
    int base = 0;
    for (int j0 = 0; j0 < NN; j0 += 32) {
        int   j    = j0 + lane;
        float v    = adj[(size_t)row * NN + j];
        bool  pres = (v != 0.f) || (j == row);
        float aval = v + ((j == row) ? 1.f : 0.f);
        unsigned m = __ballot_sync(0xffffffffu, pres);
        if (pres) {
            int pos = base + __popc(m & ((1u << lane) - 1u));
            if (pos < MAXW)
                g_cv[row * MAXW + pos] = make_int2(j, __float_as_int(aval * dr * g_dinv[j]));
        }
        base += __popc(m);
    }
    if (base > MAXW) base = MAXW;
    if (lane == 0) g_len[row] = base;
}

// weight packing + A@x precompute, one kernel
__global__ void k_prep(const float* __restrict__ x,
                       const float* gcWi0, const float* gcWh0, const float* liWi0, const float* liWh0,
                       const float* gcWi1, const float* liWi1, const float* gcWh1, const float* liWh1,
                       const float* bi0, const float* bh0, const float* lbi0, const float* lbh0,
                       const float* bi1, const float* bh1, const float* lbi1, const float* lbh1) {
    int idx = blockIdx.x * blockDim.x + threadIdx.x;
    const int W0E = 128 * C4, W1E = 256 * C4, WXE = 4 * C4;
    if (idx < W0E) {
        int r = idx >> 8, c = idx & 255;
        g_W0[idx] = (r < 64) ? gcWh0[r * C4 + c] : liWh0[(r - 64) * C4 + c];
    } else if (idx < W0E + W1E) {
        int j = idx - W0E; int r = j >> 8, c = j & 255;
        int seg = r >> 6, rr = r & 63;
        const float* s = (seg == 0) ? gcWi1 : (seg == 1) ? liWi1 : (seg == 2) ? gcWh1 : liWh1;
        g_W1[j] = s[rr * C4 + c];
    } else if (idx < W0E + W1E + WXE) {
        int j = idx - W0E - W1E; int q = j >> 8, c = j & 255;
        g_Wx0[j] = (q < 2) ? gcWi0[q * C4 + c] : liWi0[(q - 2) * C4 + c];
    } else if (idx < W0E + W1E + WXE + C4) {
        int c = idx - (W0E + W1E + WXE);
        g_b0[c] = bi0[c] + bh0[c] + lbi0[c] + lbh0[c];
    } else if (idx < W0E + W1E + WXE + 2 * C4) {
        int c = idx - (W0E + W1E + WXE + C4);
        g_b1[c] = bi1[c] + bh1[c] + lbi1[c] + lbh1[c];
    }
    // A @ x for all timesteps
    if (idx < TT * NN) {
        int t = idx / NN, i = idx - t * NN;
        int len = g_len[i];
        const int2* cp = g_cv + (size_t)i * MAXW;
        float a0 = 0.f, a1 = 0.f;
        for (int k = 0; k < len; k++) {
            int2 cv = cp[k];
            float v = __int_as_float(cv.y);
            float2 xv = *(const float2*)&x[(size_t)t * (NN * 2) + cv.x * 2];
            a0 += v * xv.x; a1 += v * xv.y;
        }
        *(float2*)&g_AX[((size_t)t * NN + i) * 2] = make_float2(a0, a1);
    }
}

__global__ void k_zero() {
    int idx = blockIdx.x * blockDim.x + threadIdx.x;
    if (idx < NN * HH) {
        g_h0[0][idx] = 0.f; g_c0[0][idx] = 0.f;
        g_h1[0][idx] = 0.f; g_c1[0][idx] = 0.f;
        g_bh0[0][idx] = __float2bfloat16(0.f);
        g_bh1[0][idx] = __float2bfloat16(0.f);
    }
}

// ================= cell 0: Ah0 gather + [Ah0|h0]@W0 + [AX|x]@Wx0 + gates =================
// dynamic smem: su[28][128] | sW[2][16][256] (=comb) | sWx[4][256] | sx[28][4]
#define C0_SU   0
#define C0_SW   (ROWS * 128)
#define C0_SWX  (C0_SW + 2 * 16 * C4)
#define C0_SX   (C0_SWX + 4 * C4)
#define C0_SMEM ((C0_SX + ROWS * 4) * 4)

__global__ __launch_bounds__(NTHR) void k_cell0(const float* __restrict__ x, int t, int pin, int pout) {
    extern __shared__ __align__(16) float smem[];
    float (*su)[128]     = (float(*)[128])(smem + C0_SU);
    float (*sW)[16][C4]  = (float(*)[16][C4])(smem + C0_SW);
    float* cw            = smem + C0_SW;                 // comb aliases sW
    float (*sWx)[C4]     = (float(*)[C4])(smem + C0_SWX);
    float (*sx)[4]       = (float(*)[4])(smem + C0_SX);

    const int tid  = threadIdx.x;
    const int row0 = blockIdx.x * ROWS;
    const float* __restrict__ h0o = g_h0[pin];
    const __nv_bfloat16* __restrict__ bin = g_bh0[pin];

    // stage h0_old rows (fp32) -> su[:,64:128)
    {
        int r = tid >> 4, q = tid & 15;
        int grow = min(row0 + r, NN - 1);
        *(float4*)&su[r][64 + q * 4] = *(const float4*)&h0o[(size_t)grow * HH + q * 4];
    }
    if (tid < 256) {                     // sWx (4x256)
        int kk = tid >> 6, q = tid & 63;
        *(float4*)&sWx[kk][q * 4] = *(const float4*)&g_Wx0[kk * C4 + q * 4];
    }
    if (tid < ROWS) {                    // x-term inputs
        int grow = min(row0 + tid, NN - 1);
        float2 axv = *(const float2*)&g_AX[((size_t)t * NN + grow) * 2];
        float2 xv  = *(const float2*)&x[(size_t)t * (NN * 2) + grow * 2];
        sx[tid][0] = axv.x; sx[tid][1] = axv.y;
        sx[tid][2] = xv.x;  sx[tid][3] = xv.y;
    }
    // prefetch W tile 0 into regs (latency hidden behind the gather)
    const float4* W4 = (const float4*)g_W0;
    float4 pf0 = W4[tid], pf1 = W4[tid + 448], pf2;
    if (tid < 128) pf2 = W4[tid + 896];

    // gather (A @ h0_old, bf16) -> su[:,0:64)
    {
        const int row = tid >> 4, lane = tid & 15;
        const int grow = min(row0 + row, NN - 1);
        const int len = g_len[grow];
        const int2* cb = g_cv + (size_t)grow * MAXW;
        float4 a4 = make_float4(0.f, 0.f, 0.f, 0.f);
        #pragma unroll 4
        for (int k = 0; k < len; k++) {
            int2 cv = __ldg(&cb[k]);
            gacc(a4, __int_as_float(cv.y), bin, cv.x, lane);
        }
        *(float4*)&su[row][lane * 4] = a4;
    }
    // store W tile 0
    {
        float4* s4 = (float4*)sW[0];
        s4[tid] = pf0; s4[tid + 448] = pf1; if (tid < 128) s4[tid + 896] = pf2;
    }
    __syncthreads();

    // GEMM: [28 x 128] @ [128 x 256]; thread = 4 rows x 4 cols
    const int cg = tid & 63, rg = tid >> 6;      // rg 0..6
    const int c0 = cg * 4, r0 = rg * 4;
    ull acc[4][2];
    {
        float4 bb = *(const float4*)&g_b0[c0];
        ull b01 = pack2(bb.x, bb.y), b23 = pack2(bb.z, bb.w);
        #pragma unroll
        for (int r = 0; r < 4; r++) { acc[r][0] = b01; acc[r][1] = b23; }
        // x-term (K = 4)
        #pragma unroll
        for (int q = 0; q < 4; q++) {
            float4 wv = *(const float4*)&sWx[q][c0];
            ull w01 = pack2(wv.x, wv.y), w23 = pack2(wv.z, wv.w);
            #pragma unroll
            for (int r = 0; r < 4; r++) {
                float uv = sx[r0 + r][q];
                ull uu = pack2(uv, uv);
                fma2(acc[r][0], uu, w01); fma2(acc[r][1], uu, w23);
            }
        }
    }
    #pragma unroll 1
    for (int kt = 0; kt < 8; kt++) {
        float4 pa, pb, pc;
        if (kt < 7) {
            const float4* Wn = W4 + (size_t)(kt + 1) * 1024;
            pa = Wn[tid]; pb = Wn[tid + 448]; if (tid < 128) pc = Wn[tid + 896];
        }
        const float (*sWb)[C4] = sW[kt & 1];
        #pragma unroll
        for (int kq = 0; kq < 4; kq++) {
            int kb = kt * 16 + kq * 4;
            float uq[4][4];
            #pragma unroll
            for (int r = 0; r < 4; r++) *(float4*)uq[r] = *(const float4*)&su[r0 + r][kb];
            #pragma unroll
            for (int j = 0; j < 4; j++) {
                float4 wv = *(const float4*)&sWb[kq * 4 + j][c0];
                ull w01 = pack2(wv.x, wv.y), w23 = pack2(wv.z, wv.w);
                #pragma unroll
                for (int r = 0; r < 4; r++) {
                    ull uu = pack2(uq[r][j], uq[r][j]);
                    fma2(acc[r][0], uu, w01); fma2(acc[r][1], uu, w23);
                }
            }
        }
        if (kt < 7) {
            float4* s4 = (float4*)sW[(kt + 1) & 1];
            s4[tid] = pa; s4[tid + 448] = pb; if (tid < 128) s4[tid + 896] = pc;
        }
        __syncthreads();                 // single sync per tile
    }

    // comb -> reuse sW storage as [28][256], then gates
    #pragma unroll
    for (int r = 0; r < 4; r++) {
        float a, b;
        unpack2(acc[r][0], a, b); *(float2*)&cw[(r0 + r) * C4 + c0]     = make_float2(a, b);
        unpack2(acc[r][1], a, b); *(float2*)&cw[(r0 + r) * C4 + c0 + 2] = make_float2(a, b);
    }
    __syncthreads();

    const float* __restrict__ cold = g_c0[pin];
    float* __restrict__ hn = g_h0[pout];
    float* __restrict__ cn = g_c0[pout];
    __nv_bfloat16* __restrict__ bo = g_bh0[pout];
    #pragma unroll
    for (int it = 0; it < 4; it++) {
        int i = tid + it * NTHR;             // 28*64 = 1792 = 4*448
        int r = i >> 6, h = i & 63;
        int grow = row0 + r;
        if (grow < NN) {
            float ig = cw[r * C4 + h],       fg = cw[r * C4 + 64 + h];
            float og = cw[r * C4 + 128 + h], gg = cw[r * C4 + 192 + h];
            size_t gi = (size_t)grow * HH + h;
            float cvv = sigf(fg) * cold[gi] + sigf(ig) * tanhf2(gg);
            cn[gi] = cvv;
            float hv = sigf(og) * tanhf2(cvv);
            hn[gi] = hv;
            bo[gi] = __float2bfloat16(hv);
        }
    }
}

// ================= cell 1: gathers + [Ah0|h0|Ah1|h1]@W1 + gates =================
// dynamic smem: su[28][256] | sW[2][16][256] (=comb)
#define C1_SU   0
#define C1_SW   (ROWS * C4)
#define C1_SMEM ((C1_SW + 2 * 16 * C4) * 4)

__global__ __launch_bounds__(NTHR) void k_cell1(int pin, int pout) {
    extern __shared__ __align__(16) float smem[];
    float (*su)[C4]     = (float(*)[C4])(smem + C1_SU);
    float (*sW)[16][C4] = (float(*)[16][C4])(smem + C1_SW);
    float* cw           = smem + C1_SW;

    const int tid  = threadIdx.x;
    const int row0 = blockIdx.x * ROWS;
    const float* __restrict__ h0n = g_h0[pout];   // new h0 from cell0 this step
    const float* __restrict__ h1o = g_h1[pin];
    const __nv_bfloat16* __restrict__ bin0 = g_bh0[pout];
    const __nv_bfloat16* __restrict__ bin1 = g_bh1[pin];

    // stage h0n -> su[:,64:128), h1o -> su[:,192:256)  (fp32 direct operands)
    {
        int r = tid >> 4, q = tid & 15;
        int grow = min(row0 + r, NN - 1);
        *(float4*)&su[r][64  + q * 4] = *(const float4*)&h0n[(size_t)grow * HH + q * 4];
        *(float4*)&su[r][192 + q * 4] = *(const float4*)&h1o[(size_t)grow * HH + q * 4];
    }
    // prefetch W tile 0
    const float4* W4 = (const float4*)g_W1;
    float4 pf0 = W4[tid], pf1 = W4[tid + 448], pf2;
    if (tid < 128) pf2 = W4[tid + 896];

    // gather A@h0n -> su[:,0:64), A@h1o -> su[:,128:192)  (bf16 mirrors)
    {
        const int row = tid >> 4, lane = tid & 15;
        const int grow = min(row0 + row, NN - 1);
        const int len = g_len[grow];
        const int2* cb = g_cv + (size_t)grow * MAXW;
        float4 a0 = make_float4(0.f, 0.f, 0.f, 0.f);
        float4 a1 = make_float4(0.f, 0.f, 0.f, 0.f);
        #pragma unroll 4
        for (int k = 0; k < len; k++) {
            int2 cv = __ldg(&cb[k]);
            float v = __int_as_float(cv.y);
            gacc(a0, v, bin0, cv.x, lane);
            gacc(a1, v, bin1, cv.x, lane);
        }
        *(float4*)&su[row][lane * 4]       = a0;
        *(float4*)&su[row][128 + lane * 4] = a1;
    }
    {
        float4* s4 = (float4*)sW[0];
        s4[tid] = pf0; s4[tid + 448] = pf1; if (tid < 128) s4[tid + 896] = pf2;
    }
    __syncthreads();

    // GEMM: [28 x 256] @ [256 x 256]
    const int cg = tid & 63, rg = tid >> 6;
    const int c0 = cg * 4, r0 = rg * 4;
    ull acc[4][2];
    {
        float4 bb = *(const float4*)&g_b1[c0];
        ull b01 = pack2(bb.x, bb.y), b23 = pack2(bb.z, bb.w);
        #pragma unroll
        for (int r = 0; r < 4; r++) { acc[r][0] = b01; acc[r][1] = b23; }
    }
    #pragma unroll 1
    for (int kt = 0; kt < 16; kt++) {
        float4 pa, pb, pc;
        if (kt < 15) {
            const float4* Wn = W4 + (size_t)(kt + 1) * 1024;
            pa = Wn[tid]; pb = Wn[tid + 448]; if (tid < 128) pc = Wn[tid + 896];
        }
        const float (*sWb)[C4] = sW[kt & 1];
        #pragma unroll
        for (int kq = 0; kq < 4; kq++) {
            int kb = kt * 16 + kq * 4;
            float uq[4][4];
            #pragma unroll
            for (int r = 0; r < 4; r++) *(float4*)uq[r] = *(const float4*)&su[r0 + r][kb];
            #pragma unroll
            for (int j = 0; j < 4; j++) {
                float4 wv = *(const float4*)&sWb[kq * 4 + j][c0];
                ull w01 = pack2(wv.x, wv.y), w23 = pack2(wv.z, wv.w);
                #pragma unroll
                for (int r = 0; r < 4; r++) {
                    ull uu = pack2(uq[r][j], uq[r][j]);
                    fma2(acc[r][0], uu, w01); fma2(acc[r][1], uu, w23);
                }
            }
        }
        if (kt < 15) {
            float4* s4 = (float4*)sW[(kt + 1) & 1];
            s4[tid] = pa; s4[tid + 448] = pb; if (tid < 128) s4[tid + 896] = pc;
        }
        __syncthreads();                 // single sync per tile
    }

    // comb -> reuse sW storage, then gates
    #pragma unroll
    for (int r = 0; r < 4; r++) {
        float a, b;
        unpack2(acc[r][0], a, b); *(float2*)&cw[(r0 + r) * C4 + c0]     = make_float2(a, b);
        unpack2(acc[r][1], a, b); *(float2*)&cw[(r0 + r) * C4 + c0 + 2] = make_float2(a, b);
    }
    __syncthreads();

    const float* __restrict__ cold = g_c1[pin];
    float* __restrict__ hn = g_h1[pout];
    float* __restrict__ cn = g_c1[pout];
    __nv_bfloat16* __restrict__ bo = g_bh1[pout];
    #pragma unroll
    for (int it = 0; it < 4; it++) {
        int i = tid + it * NTHR;
        int r = i >> 6, h = i & 63;
        int grow = row0 + r;
        if (grow < NN) {
            float ig = cw[r * C4 + h],       fg = cw[r * C4 + 64 + h];
            float og = cw[r * C4 + 128 + h], gg = cw[r * C4 + 192 + h];
            size_t gi = (size_t)grow * HH + h;
            float cvv = sigf(fg) * cold[gi] + sigf(ig) * tanhf2(gg);
            cn[gi] = cvv;
            float hv = sigf(og) * tanhf2(cvv);
            hn[gi] = hv;
            bo[gi] = __float2bfloat16(hv);
        }
    }
}

// ---------------- output projection: h1 @ outW + outb ----------------
__global__ void k_out(const float* __restrict__ outW, const float* __restrict__ outb,
                      float* __restrict__ out, int hbuf) {
    int idx = blockIdx.x * blockDim.x + threadIdx.x;
    if (idx >= NN * 12) return;
    int n = idx / 12, p = idx - n * 12;
    const float* h = g_h1[hbuf] + (size_t)n * HH;
    float s = outb[p];
    #pragma unroll
    for (int k = 0; k < HH; k++) s += h[k] * outW[k * 12 + p];
    out[idx] = s;
}

extern "C" void kernel_launch(void* const* d_in, const int* in_sizes, int n_in,
                              void* d_out, int out_size) {
    const float* x     = (const float*)d_in[0];
    const float* adj   = (const float*)d_in[1];
    const float* gcWi0 = (const float*)d_in[2];
    const float* gcbi0 = (const float*)d_in[3];
    const float* gcWh0 = (const float*)d_in[4];
    const float* gcbh0 = (const float*)d_in[5];
    const float* liWi0 = (const float*)d_in[6];
    const float* libi0 = (const float*)d_in[7];
    const float* liWh0 = (const float*)d_in[8];
    const float* libh0 = (const float*)d_in[9];
    const float* gcWi1 = (const float*)d_in[10];
    const float* gcbi1 = (const float*)d_in[11];
    const float* gcWh1 = (const float*)d_in[12];
    const float* gcbh1 = (const float*)d_in[13];
    const float* liWi1 = (const float*)d_in[14];
    const float* libi1 = (const float*)d_in[15];
    const float* liWh1 = (const float*)d_in[16];
    const float* libh1 = (const float*)d_in[17];
    const float* outW  = (const float*)d_in[18];
    const float* outb  = (const float*)d_in[19];
    float* out = (float*)d_out;

    cudaFuncSetAttribute(k_cell0, cudaFuncAttributeMaxDynamicSharedMemorySize, C0_SMEM);
    cudaFuncSetAttribute(k_cell1, cudaFuncAttributeMaxDynamicSharedMemorySize, C1_SMEM);

    k_dinv<<<NN / 8, 256>>>(adj);
    k_build<<<NN / 8, 256>>>(adj);
    k_prep<<<(TT * NN + 255) / 256, 256>>>(x,
        gcWi0, gcWh0, liWi0, liWh0, gcWi1, liWi1, gcWh1, liWh1,
        gcbi0, gcbh0, libi0, libh0, gcbi1, gcbh1, libi1, libh1);
    k_zero<<<(NN * HH + 255) / 256, 256>>>();

    for (int t = 0; t < TT; t++) {
        int pin = t & 1, pout = pin ^ 1;
        k_cell0<<<GRID, NTHR, C0_SMEM>>>(x, t, pin, pout);
        k_cell1<<<GRID, NTHR, C1_SMEM>>>(pin, pout);
    }
    // after t=47: pout = 0 -> final h1 in buffer 0
    k_out<<<(NN * 12 + 255) / 256, 256>>>(outW, outb, out, 0);
}

// round 12
// speedup vs baseline: 1.5037x; 1.3191x over previous
#include <cuda_runtime.h>
#include <cuda_bf16.h>

#define NN   4096
#define TT   48
#define HH   64
#define C4   256
#define MAXW 128
#define ROWS 28
#define NTHR 512
#define GRID 147

#define SUP0 152      // su pitch (bf16) cell0: K=144 + 8 pad
#define NKT0 9        // 144/16
#define SUP1 264      // su pitch (bf16) cell1: K=256 + 8 pad
#define NKT1 16
#define CWP  260      // comb pitch (fp32)

typedef unsigned long long ull;

// ---------------- device scratch (no allocations allowed) ----------------
__device__ __align__(16) float g_dinv[NN];
__device__ __align__(16) int2  g_cv[NN * MAXW];    // (col, __float_as_int(val))
__device__ __align__(16) int   g_len[NN];
__device__ __align__(16) float g_AX[TT * NN * 2];
__device__ __align__(16) __nv_bfloat16 g_Wp0[144 * C4];  // fragment-packed [gcWh0;liWh0;Wx;0]
__device__ __align__(16) __nv_bfloat16 g_Wp1[256 * C4];  // fragment-packed [gcWi1;liWi1;gcWh1;liWh1]
__device__ __align__(16) float g_b0[C4];
__device__ __align__(16) float g_b1[C4];
__device__ __align__(16) float g_c0[2][NN * HH];
__device__ __align__(16) float g_c1[2][NN * HH];
__device__ __align__(16) float g_h1f[NN * HH];           // fp32 h1 (for output proj)
__device__ __align__(16) __nv_bfloat16 g_bh0[2][NN * HH];  // bf16 h mirrors (all GEMM/gather A ops)
__device__ __align__(16) __nv_bfloat16 g_bh1[2][NN * HH];

// ---------------- helpers ----------------
__device__ __forceinline__ float sigf(float v)  { return 1.f / (1.f + __expf(-v)); }
__device__ __forceinline__ float tanhf2(float v){ return 2.f / (1.f + __expf(-2.f * v)) - 1.f; }

// gather 4 bf16 (8 B = one L2 sector per 16-lane row group)
__device__ __forceinline__ void gacc(float4& a, float v, const __nv_bfloat16* bh, int c, int lane) {
    uint2 raw = *((const uint2*)(bh + (size_t)c * HH) + lane);
    __nv_bfloat162 b01 = *(__nv_bfloat162*)&raw.x;
    __nv_bfloat162 b23 = *(__nv_bfloat162*)&raw.y;
    float2 f01 = __bfloat1622float2(b01), f23 = __bfloat1622float2(b23);
    a.x += v * f01.x; a.y += v * f01.y; a.z += v * f23.x; a.w += v * f23.y;
}

__device__ __forceinline__ uint2 f4_to_b4(float4 a) {
    __nv_bfloat162 lo = __floats2bfloat162_rn(a.x, a.y);
    __nv_bfloat162 hi = __floats2bfloat162_rn(a.z, a.w);
    uint2 r; r.x = *(unsigned*)&lo; r.y = *(unsigned*)&hi; return r;
}

// mma.sync m16n8k16 row.col f32.bf16.bf16.f32
__device__ __forceinline__ void mma_bf16(float* c, unsigned a0, unsigned a1, unsigned a2, unsigned a3,
                                         unsigned b0, unsigned b1) {
    asm volatile("mma.sync.aligned.m16n8k16.row.col.f32.bf16.bf16.f32 "
                 "{%0,%1,%2,%3},{%4,%5,%6,%7},{%8,%9},{%0,%1,%2,%3};"
                 : "+f"(c[0]), "+f"(c[1]), "+f"(c[2]), "+f"(c[3])
                 : "r"(a0), "r"(a1), "r"(a2), "r"(a3), "r"(b0), "r"(b1));
}

// fragment-packed weight offset for element (k, n): B fragment of mma m16n8k16
// tile = (nt * nkt + kt), 128 bf16 per tile; within tile: thread t = nr*4 + ((kr&7)>>1),
// pos = t*4 + (kr>>3)*2 + (kr&1)
__host__ __device__ __forceinline__ int fragoff(int k, int n, int nkt) {
    int kt = k >> 4, kr = k & 15, nt = n >> 3, nr = n & 7;
    int t = nr * 4 + ((kr & 7) >> 1);
    int pos = t * 4 + ((kr >> 3) << 1) + (kr & 1);
    return ((nt * nkt + kt) << 7) + pos;
}

// ---------------- setup kernels ----------------
__global__ void k_dinv(const float* __restrict__ adj) {
    int row  = blockIdx.x * 8 + (threadIdx.x >> 5);
    int lane = threadIdx.x & 31;
    if (row >= NN) return;
    float s = 0.f;
    for (int j = lane; j < NN; j += 32) s += adj[(size_t)row * NN + j];
    #pragma unroll
    for (int o = 16; o; o >>= 1) s += __shfl_xor_sync(0xffffffffu, s, o);
    if (lane == 0) g_dinv[row] = rsqrtf(s + 1.f);   // A = adj + I
}

__global__ void k_build(const float* __restrict__ adj) {
    int row  = blockIdx.x * 8 + (threadIdx.x >> 5);
    int lane = threadIdx.x & 31;
    if (row >= NN) return;
    float dr = g_dinv[row];
    int base = 0;
    for (int j0 = 0; j0 < NN; j0 += 32) {
        int   j    = j0 + lane;
        float v    = adj[(size_t)row * NN + j];
        bool  pres = (v != 0.f) || (j == row);
        float aval = v + ((j == row) ? 1.f : 0.f);
        unsigned m = __ballot_sync(0xffffffffu, pres);
        if (pres) {
            int pos = base + __popc(m & ((1u << lane) - 1u));
            if (pos < MAXW)
                g_cv[row * MAXW + pos] = make_int2(j, __float_as_int(aval * dr * g_dinv[j]));
        }
        base += __popc(m);
    }
    if (base > MAXW) base = MAXW;
    if (lane == 0) g_len[row] = base;
}

// pack fragment weights (bf16) + biases + zero state + A@x, one kernel
__global__ void k_prep(const float* __restrict__ x,
                       const float* gcWi0, const float* gcWh0, const float* liWi0, const float* liWh0,
                       const float* gcWi1, const float* liWi1, const float* gcWh1, const float* liWh1,
                       const float* bi0, const float* bh0, const float* lbi0, const float* lbh0,
                       const float* bi1, const float* bh1, const float* lbi1, const float* lbh1) {
    int idx = blockIdx.x * blockDim.x + threadIdx.x;
    const int W0E = 144 * C4, W1E = 256 * C4;
    int o = idx;
    if (o < W0E) {
        int k = o >> 8, n = o & 255;
        float v;
        if (k < 64)       v = gcWh0[k * C4 + n];
        else if (k < 128) v = liWh0[(k - 64) * C4 + n];
        else {
            int q = k - 128;
            v = (q < 2) ? gcWi0[q * C4 + n] : (q < 4) ? liWi0[(q - 2) * C4 + n] : 0.f;
        }
        g_Wp0[fragoff(k, n, NKT0)] = __float2bfloat16(v);
        return;
    }
    o -= W0E;
    if (o < W1E) {
        int k = o >> 8, n = o & 255;
        int seg = k >> 6, rr = k & 63;
        const float* s = (seg == 0) ? gcWi1 : (seg == 1) ? liWi1 : (seg == 2) ? gcWh1 : liWh1;
        g_Wp1[fragoff(k, n, NKT1)] = __float2bfloat16(s[rr * C4 + n]);
        return;
    }
    o -= W1E;
    if (o < C4) { g_b0[o] = bi0[o] + bh0[o] + lbi0[o] + lbh0[o]; return; }
    o -= C4;
    if (o < C4) { g_b1[o] = bi1[o] + bh1[o] + lbi1[o] + lbh1[o]; return; }
    o -= C4;
    if (o < NN * HH) {
        g_c0[0][o] = 0.f; g_c1[0][o] = 0.f;
        g_bh0[0][o] = __float2bfloat16(0.f);
        g_bh1[0][o] = __float2bfloat16(0.f);
        return;
    }
    o -= NN * HH;
    if (o < TT * NN) {
        int t = o / NN, i = o - t * NN;
        int len = g_len[i];
        const int2* cp = g_cv + (size_t)i * MAXW;
        float a0 = 0.f, a1 = 0.f;
        for (int k = 0; k < len; k++) {
            int2 cv = cp[k];
            float v = __int_as_float(cv.y);
            float2 xv = *(const float2*)&x[(size_t)t * (NN * 2) + cv.x * 2];
            a0 += v * xv.x; a1 += v * xv.y;
        }
        *(float2*)&g_AX[((size_t)t * NN + i) * 2] = make_float2(a0, a1);
    }
}
#define PREP_TOTAL (144 * C4 + 256 * C4 + 2 * C4 + NN * HH + TT * NN)

// ================= cell 0: gather + mma [28x144]@[144x256] + gates =================
// smem: su bf16[32][SUP0] | cw f32[32][CWP]
#define C0_SMEM (32 * SUP0 * 2 + 32 * CWP * 4)

__global__ __launch_bounds__(NTHR) void k_cell0(const float* __restrict__ x, int t, int pin, int pout) {
    extern __shared__ __align__(16) char smem[];
    __nv_bfloat16* su = (__nv_bfloat16*)smem;
    float* cw = (float*)(smem + 32 * SUP0 * 2);

    const int tid  = threadIdx.x;
    const int row0 = blockIdx.x * ROWS;
    const __nv_bfloat16* __restrict__ bin = g_bh0[pin];

    // zero su (covers row pad 28-31 and K pad 132-151)
    {
        uint4* p = (uint4*)su;                 // 32*SUP0*2/16 = 608
        for (int i = tid; i < 32 * SUP0 / 8; i += NTHR) p[i] = make_uint4(0, 0, 0, 0);
    }
    __syncthreads();

    // stage direct h0 (bf16) -> su[:,64:128); x-term -> su[:,128:132)
    if (tid < 448) {
        int r = tid >> 4, lane = tid & 15;
        int grow = min(row0 + r, NN - 1);
        uint2 v0 = *((const uint2*)(bin + (size_t)grow * HH) + lane);
        *(uint2*)&su[r * SUP0 + 64 + lane * 4] = v0;
    }
    if (tid < ROWS) {
        int grow = min(row0 + tid, NN - 1);
        float2 axv = *(const float2*)&g_AX[((size_t)t * NN + grow) * 2];
        float2 xv  = *(const float2*)&x[(size_t)t * (NN * 2) + grow * 2];
        *(uint2*)&su[tid * SUP0 + 128] = f4_to_b4(make_float4(axv.x, axv.y, xv.x, xv.y));
    }
    // gather A@h0_old -> su[:,0:64)
    if (tid < 448) {
        int r = tid >> 4, lane = tid & 15;
        int grow = min(row0 + r, NN - 1);
        int len = g_len[grow];
        const int2* cb = g_cv + (size_t)grow * MAXW;
        float4 a4 = make_float4(0.f, 0.f, 0.f, 0.f);
        #pragma unroll 4
        for (int k = 0; k < len; k++) {
            int2 cv = __ldg(&cb[k]);
            gacc(a4, __int_as_float(cv.y), bin, cv.x, lane);
        }
        *(uint2*)&su[r * SUP0 + lane * 4] = f4_to_b4(a4);
    }
    __syncthreads();

    // MMA: 16 warps = 2 m-tiles x 8 n-chunks(32)
    {
        const int w = tid >> 5, tl = tid & 31;
        const int mt = w & 1, nc = w >> 1;
        const int rA = mt * 16 + (tl >> 2);
        const int cA = 2 * (tl & 3);
        float c[4][4];
        #pragma unroll
        for (int j = 0; j < 4; j++) { c[j][0] = c[j][1] = c[j][2] = c[j][3] = 0.f; }
        #pragma unroll 1
        for (int kt = 0; kt < NKT0; kt++) {
            unsigned a0 = *(const unsigned*)&su[rA * SUP0 + kt * 16 + cA];
            unsigned a1 = *(const unsigned*)&su[(rA + 8) * SUP0 + kt * 16 + cA];
            unsigned a2 = *(const unsigned*)&su[rA * SUP0 + kt * 16 + cA + 8];
            unsigned a3 = *(const unsigned*)&su[(rA + 8) * SUP0 + kt * 16 + cA + 8];
            #pragma unroll
            for (int j = 0; j < 4; j++) {
                int nt = nc * 4 + j;
                uint2 b = __ldg((const uint2*)g_Wp0 + (nt * NKT0 + kt) * 32 + tl);
                mma_bf16(c[j], a0, a1, a2, a3, b.x, b.y);
            }
        }
        // bias + comb -> cw
        int r = mt * 16 + (tl >> 2);
        #pragma unroll
        for (int j = 0; j < 4; j++) {
            int n = nc * 32 + j * 8 + 2 * (tl & 3);
            float2 bb = *(const float2*)&g_b0[n];
            cw[r * CWP + n]           = c[j][0] + bb.x;
            cw[r * CWP + n + 1]       = c[j][1] + bb.y;
            cw[(r + 8) * CWP + n]     = c[j][2] + bb.x;
            cw[(r + 8) * CWP + n + 1] = c[j][3] + bb.y;
        }
    }
    __syncthreads();

    // gates -> c0 fp32 + h0 bf16 mirror
    const float* __restrict__ cold = g_c0[pin];
    float* __restrict__ cn = g_c0[pout];
    __nv_bfloat16* __restrict__ bo = g_bh0[pout];
    for (int i = tid; i < ROWS * HH; i += NTHR) {
        int r = i >> 6, h = i & 63;
        int grow = row0 + r;
        if (grow < NN) {
            float ig = cw[r * CWP + h],       fg = cw[r * CWP + 64 + h];
            float og = cw[r * CWP + 128 + h], gg = cw[r * CWP + 192 + h];
            size_t gi = (size_t)grow * HH + h;
            float cvv = sigf(fg) * cold[gi] + sigf(ig) * tanhf2(gg);
            cn[gi] = cvv;
            bo[gi] = __float2bfloat16(sigf(og) * tanhf2(cvv));
        }
    }
}

// ================= cell 1: gathers + mma [28x256]@[256x256] + gates =================
// smem: su bf16[32][SUP1] | cw f32[32][CWP]
#define C1_SMEM (32 * SUP1 * 2 + 32 * CWP * 4)

__global__ __launch_bounds__(NTHR) void k_cell1(int pin, int pout) {
    extern __shared__ __align__(16) char smem[];
    __nv_bfloat16* su = (__nv_bfloat16*)smem;
    float* cw = (float*)(smem + 32 * SUP1 * 2);

    const int tid  = threadIdx.x;
    const int row0 = blockIdx.x * ROWS;
    const __nv_bfloat16* __restrict__ bin0 = g_bh0[pout];   // new h0 (this step)
    const __nv_bfloat16* __restrict__ bin1 = g_bh1[pin];    // old h1

    // zero su
    {
        uint4* p = (uint4*)su;                 // 32*SUP1*2/16 = 1056
        for (int i = tid; i < 32 * SUP1 / 8; i += NTHR) p[i] = make_uint4(0, 0, 0, 0);
    }
    __syncthreads();

    // stage direct h: h0n -> su[:,64:128), h1o -> su[:,192:256)
    if (tid < 448) {
        int r = tid >> 4, lane = tid & 15;
        int grow = min(row0 + r, NN - 1);
        uint2 v0 = *((const uint2*)(bin0 + (size_t)grow * HH) + lane);
        uint2 v1 = *((const uint2*)(bin1 + (size_t)grow * HH) + lane);
        *(uint2*)&su[r * SUP1 + 64 + lane * 4]  = v0;
        *(uint2*)&su[r * SUP1 + 192 + lane * 4] = v1;
    }
    // gather A@h0n -> su[:,0:64), A@h1o -> su[:,128:192)
    if (tid < 448) {
        int r = tid >> 4, lane = tid & 15;
        int grow = min(row0 + r, NN - 1);
        int len = g_len[grow];
        const int2* cb = g_cv + (size_t)grow * MAXW;
        float4 a0 = make_float4(0.f, 0.f, 0.f, 0.f);
        float4 a1 = make_float4(0.f, 0.f, 0.f, 0.f);
        #pragma unroll 4
        for (int k = 0; k < len; k++) {
            int2 cv = __ldg(&cb[k]);
            float v = __int_as_float(cv.y);
            gacc(a0, v, bin0, cv.x, lane);
            gacc(a1, v, bin1, cv.x, lane);
        }
        *(uint2*)&su[r * SUP1 + lane * 4]       = f4_to_b4(a0);
        *(uint2*)&su[r * SUP1 + 128 + lane * 4] = f4_to_b4(a1);
    }
    __syncthreads();

    // MMA
    {
        const int w = tid >> 5, tl = tid & 31;
        const int mt = w & 1, nc = w >> 1;
        const int rA = mt * 16 + (tl >> 2);
        const int cA = 2 * (tl & 3);
        float c[4][4];
        #pragma unroll
        for (int j = 0; j < 4; j++) { c[j][0] = c[j][1] = c[j][2] = c[j][3] = 0.f; }
        #pragma unroll 1
        for (int kt = 0; kt < NKT1; kt++) {
            unsigned a0 = *(const unsigned*)&su[rA * SUP1 + kt * 16 + cA];
            unsigned a1 = *(const unsigned*)&su[(rA + 8) * SUP1 + kt * 16 + cA];
            unsigned a2 = *(const unsigned*)&su[rA * SUP1 + kt * 16 + cA + 8];
            unsigned a3 = *(const unsigned*)&su[(rA + 8) * SUP1 + kt * 16 + cA + 8];
            #pragma unroll
            for (int j = 0; j < 4; j++) {
                int nt = nc * 4 + j;
                uint2 b = __ldg((const uint2*)g_Wp1 + (nt * NKT1 + kt) * 32 + tl);
                mma_bf16(c[j], a0, a1, a2, a3, b.x, b.y);
            }
        }
        int r = mt * 16 + (tl >> 2);
        #pragma unroll
        for (int j = 0; j < 4; j++) {
            int n = nc * 32 + j * 8 + 2 * (tl & 3);
            float2 bb = *(const float2*)&g_b1[n];
            cw[r * CWP + n]           = c[j][0] + bb.x;
            cw[r * CWP + n + 1]       = c[j][1] + bb.y;
            cw[(r + 8) * CWP + n]     = c[j][2] + bb.x;
            cw[(r + 8) * CWP + n + 1] = c[j][3] + bb.y;
        }
    }
    __syncthreads();

    // gates -> c1 fp32 + h1 (fp32 + bf16 mirror)
    const float* __restrict__ cold = g_c1[pin];
    float* __restrict__ cn = g_c1[pout];
    __nv_bfloat16* __restrict__ bo = g_bh1[pout];
    for (int i = tid; i < ROWS * HH; i += NTHR) {
        int r = i >> 6, h = i & 63;
        int grow = row0 + r;
        if (grow < NN) {
            float ig = cw[r * CWP + h],       fg = cw[r * CWP + 64 + h];
            float og = cw[r * CWP + 128 + h], gg = cw[r * CWP + 192 + h];
            size_t gi = (size_t)grow * HH + h;
            float cvv = sigf(fg) * cold[gi] + sigf(ig) * tanhf2(gg);
            cn[gi] = cvv;
            float hv = sigf(og) * tanhf2(cvv);
            g_h1f[gi] = hv;
            bo[gi] = __float2bfloat16(hv);
        }
    }
}

// ---------------- output projection: h1 @ outW + outb ----------------
__global__ void k_out(const float* __restrict__ outW, const float* __restrict__ outb,
                      float* __restrict__ out) {
    int idx = blockIdx.x * blockDim.x + threadIdx.x;
    if (idx >= NN * 12) return;
    int n = idx / 12, p = idx - n * 12;
    const float* h = g_h1f + (size_t)n * HH;
    float s = outb[p];
    #pragma unroll
    for (int k = 0; k < HH; k++) s += h[k] * outW[k * 12 + p];
    out[idx] = s;
}

extern "C" void kernel_launch(void* const* d_in, const int* in_sizes, int n_in,
                              void* d_out, int out_size) {
    const float* x     = (const float*)d_in[0];
    const float* adj   = (const float*)d_in[1];
    const float* gcWi0 = (const float*)d_in[2];
    const float* gcbi0 = (const float*)d_in[3];
    const float* gcWh0 = (const float*)d_in[4];
    const float* gcbh0 = (const float*)d_in[5];
    const float* liWi0 = (const float*)d_in[6];
    const float* libi0 = (const float*)d_in[7];
    const float* liWh0 = (const float*)d_in[8];
    const float* libh0 = (const float*)d_in[9];
    const float* gcWi1 = (const float*)d_in[10];
    const float* gcbi1 = (const float*)d_in[11];
    const float* gcWh1 = (const float*)d_in[12];
    const float* gcbh1 = (const float*)d_in[13];
    const float* liWi1 = (const float*)d_in[14];
    const float* libi1 = (const float*)d_in[15];
    const float* liWh1 = (const float*)d_in[16];
    const float* libh1 = (const float*)d_in[17];
    const float* outW  = (const float*)d_in[18];
    const float* outb  = (const float*)d_in[19];
    float* out = (float*)d_out;

    cudaFuncSetAttribute(k_cell0, cudaFuncAttributeMaxDynamicSharedMemorySize, C0_SMEM);
    cudaFuncSetAttribute(k_cell1, cudaFuncAttributeMaxDynamicSharedMemorySize, C1_SMEM);

    k_dinv<<<NN / 8, 256>>>(adj);
    k_build<<<NN / 8, 256>>>(adj);
    k_prep<<<(PREP_TOTAL + 255) / 256, 256>>>(x,
        gcWi0, gcWh0, liWi0, liWh0, gcWi1, liWi1, gcWh1, liWh1,
        gcbi0, gcbh0, libi0, libh0, gcbi1, gcbh1, libi1, libh1);

    for (int t = 0; t < TT; t++) {
        int pin = t & 1, pout = pin ^ 1;
        k_cell0<<<GRID, NTHR, C0_SMEM>>>(x, t, pin, pout);
        k_cell1<<<GRID, NTHR, C1_SMEM>>>(pin, pout);
    }
    k_out<<<(NN * 12 + 255) / 256, 256>>>(outW, outb, out);
}

// round 13
// speedup vs baseline: 3.0026x; 1.9968x over previous
#include <cuda_runtime.h>
#include <cuda_bf16.h>

#define NN   4096
#define TT   48
#define HH   64
#define C4   256
#define MAXW 128
#define ROWS 28
#define GRID 147

#define SUP0 152      // su pitch (bf16) cell0: K=144 + 8 pad
#define NKT0 9        // 144/16
#define SUP1 264      // su pitch (bf16) cell1: K=256 + 8 pad
#define NKT1 16
#define CWP  260      // comb pitch (fp32)

// ---------------- device scratch (no allocations allowed) ----------------
__device__ __align__(16) float g_dinv[NN];
__device__ __align__(16) int2  g_cv[NN * MAXW];    // (col, __float_as_int(val))
__device__ __align__(16) int   g_len[NN];
__device__ __align__(16) float g_AX[TT * NN * 2];
__device__ __align__(16) __nv_bfloat16 g_Wp0[144 * C4];  // fragment-packed [gcWh0;liWh0;Wx;0]
__device__ __align__(16) __nv_bfloat16 g_Wp1[256 * C4];  // fragment-packed [gcWi1;liWi1;gcWh1;liWh1]
__device__ __align__(16) float g_b0[C4];
__device__ __align__(16) float g_b1[C4];
__device__ __align__(16) float g_c0[2][NN * HH];
__device__ __align__(16) float g_c1[2][NN * HH];
__device__ __align__(16) __nv_bfloat16 g_bh0[2][NN * HH];  // bf16 h mirrors
__device__ __align__(16) __nv_bfloat16 g_bh1[2][NN * HH];

// ---------------- helpers ----------------
__device__ __forceinline__ float sigf(float v)  { return 1.f / (1.f + __expf(-v)); }
__device__ __forceinline__ float tanhf2(float v){ return 2.f / (1.f + __expf(-2.f * v)) - 1.f; }

__device__ __forceinline__ void gacc(float4& a, float v, const __nv_bfloat16* bh, int c, int lane) {
    uint2 raw = *((const uint2*)(bh + (size_t)c * HH) + lane);
    __nv_bfloat162 b01 = *(__nv_bfloat162*)&raw.x;
    __nv_bfloat162 b23 = *(__nv_bfloat162*)&raw.y;
    float2 f01 = __bfloat1622float2(b01), f23 = __bfloat1622float2(b23);
    a.x += v * f01.x; a.y += v * f01.y; a.z += v * f23.x; a.w += v * f23.y;
}

__device__ __forceinline__ uint2 f4_to_b4(float4 a) {
    __nv_bfloat162 lo = __floats2bfloat162_rn(a.x, a.y);
    __nv_bfloat162 hi = __floats2bfloat162_rn(a.z, a.w);
    uint2 r; r.x = *(unsigned*)&lo; r.y = *(unsigned*)&hi; return r;
}

__device__ __forceinline__ void mma_bf16(float* c, unsigned a0, unsigned a1, unsigned a2, unsigned a3,
                                         unsigned b0, unsigned b1) {
    asm volatile("mma.sync.aligned.m16n8k16.row.col.f32.bf16.bf16.f32 "
                 "{%0,%1,%2,%3},{%4,%5,%6,%7},{%8,%9},{%0,%1,%2,%3};"
                 : "+f"(c[0]), "+f"(c[1]), "+f"(c[2]), "+f"(c[3])
                 : "r"(a0), "r"(a1), "r"(a2), "r"(a3), "r"(b0), "r"(b1));
}

__host__ __device__ __forceinline__ int fragoff(int k, int n, int nkt) {
    int kt = k >> 4, kr = k & 15, nt = n >> 3, nr = n & 7;
    int t = nr * 4 + ((kr & 7) >> 1);
    int pos = t * 4 + ((kr >> 3) << 1) + (kr & 1);
    return ((nt * nkt + kt) << 7) + pos;
}

// ---------------- setup kernels ----------------
__global__ void k_dinv(const float* __restrict__ adj) {
    int row  = blockIdx.x * 8 + (threadIdx.x >> 5);
    int lane = threadIdx.x & 31;
    if (row >= NN) return;
    float s = 0.f;
    for (int j = lane; j < NN; j += 32) s += adj[(size_t)row * NN + j];
    #pragma unroll
    for (int o = 16; o; o >>= 1) s += __shfl_xor_sync(0xffffffffu, s, o);
    if (lane == 0) g_dinv[row] = rsqrtf(s + 1.f);   // A = adj + I
}

__global__ void k_build(const float* __restrict__ adj) {
    int row  = blockIdx.x * 8 + (threadIdx.x >> 5);
    int lane = threadIdx.x & 31;
    if (row >= NN) return;
    float dr = g_dinv[row];
    int base = 0;
    for (int j0 = 0; j0 < NN; j0 += 32) {
        int   j    = j0 + lane;
        float v    = adj[(size_t)row * NN + j];
        bool  pres = (v != 0.f) || (j == row);
        float aval = v + ((j == row) ? 1.f : 0.f);
        unsigned m = __ballot_sync(0xffffffffu, pres);
        if (pres) {
            int pos = base + __popc(m & ((1u << lane) - 1u));
            if (pos < MAXW)
                g_cv[row * MAXW + pos] = make_int2(j, __float_as_int(aval * dr * g_dinv[j]));
        }
        base += __popc(m);
    }
    if (base > MAXW) base = MAXW;
    if (lane == 0) g_len[row] = base;
}

__global__ void k_prep(const float* __restrict__ x,
                       const float* gcWi0, const float* gcWh0, const float* liWi0, const float* liWh0,
                       const float* gcWi1, const float* liWi1, const float* gcWh1, const float* liWh1,
                       const float* bi0, const float* bh0, const float* lbi0, const float* lbh0,
                       const float* bi1, const float* bh1, const float* lbi1, const float* lbh1) {
    int idx = blockIdx.x * blockDim.x + threadIdx.x;
    const int W0E = 144 * C4, W1E = 256 * C4;
    int o = idx;
    if (o < W0E) {
        int k = o >> 8, n = o & 255;
        float v;
        if (k < 64)       v = gcWh0[k * C4 + n];
        else if (k < 128) v = liWh0[(k - 64) * C4 + n];
        else {
            int q = k - 128;
            v = (q < 2) ? gcWi0[q * C4 + n] : (q < 4) ? liWi0[(q - 2) * C4 + n] : 0.f;
        }
        g_Wp0[fragoff(k, n, NKT0)] = __float2bfloat16(v);
        return;
    }
    o -= W0E;
    if (o < W1E) {
        int k = o >> 8, n = o & 255;
        int seg = k >> 6, rr = k & 63;
        const float* s = (seg == 0) ? gcWi1 : (seg == 1) ? liWi1 : (seg == 2) ? gcWh1 : liWh1;
        g_Wp1[fragoff(k, n, NKT1)] = __float2bfloat16(s[rr * C4 + n]);
        return;
    }
    o -= W1E;
    if (o < C4) { g_b0[o] = bi0[o] + bh0[o] + lbi0[o] + lbh0[o]; return; }
    o -= C4;
    if (o < C4) { g_b1[o] = bi1[o] + bh1[o] + lbi1[o] + lbh1[o]; return; }
    o -= C4;
    if (o < NN * HH) {
        g_c0[0][o] = 0.f; g_c1[0][o] = 0.f;
        g_bh0[0][o] = __float2bfloat16(0.f);
        g_bh1[0][o] = __float2bfloat16(0.f);
        return;
    }
    o -= NN * HH;
    if (o < TT * NN) {
        int t = o / NN, i = o - t * NN;
        int len = g_len[i];
        const int2* cp = g_cv + (size_t)i * MAXW;
        float a0 = 0.f, a1 = 0.f;
        for (int k = 0; k < len; k++) {
            int2 cv = cp[k];
            float v = __int_as_float(cv.y);
            float2 xv = *(const float2*)&x[(size_t)t * (NN * 2) + cv.x * 2];
            a0 += v * xv.x; a1 += v * xv.y;
        }
        *(float2*)&g_AX[((size_t)t * NN + i) * 2] = make_float2(a0, a1);
    }
}
#define PREP_TOTAL (144 * C4 + 256 * C4 + 2 * C4 + NN * HH + TT * NN)

// ================= initial cell 0 (t = 0 only) =================
#define NTHR0 512
#define C0_SMEM (32 * SUP0 * 2 + 32 * CWP * 4)

__global__ __launch_bounds__(NTHR0) void k_cell0(const float* __restrict__ x, int t, int pin, int pout) {
    extern __shared__ __align__(16) char smem[];
    __nv_bfloat16* su = (__nv_bfloat16*)smem;
    float* cw = (float*)(smem + 32 * SUP0 * 2);

    const int tid  = threadIdx.x;
    const int row0 = blockIdx.x * ROWS;
    const __nv_bfloat16* __restrict__ bin = g_bh0[pin];

    {
        uint4* p = (uint4*)su;
        for (int i = tid; i < 32 * SUP0 / 8; i += NTHR0) p[i] = make_uint4(0, 0, 0, 0);
    }
    __syncthreads();

    if (tid < 448) {
        int r = tid >> 4, lane = tid & 15;
        int grow = min(row0 + r, NN - 1);
        uint2 v0 = *((const uint2*)(bin + (size_t)grow * HH) + lane);
        *(uint2*)&su[r * SUP0 + 64 + lane * 4] = v0;
    }
    if (tid < ROWS) {
        int grow = min(row0 + tid, NN - 1);
        float2 axv = *(const float2*)&g_AX[((size_t)t * NN + grow) * 2];
        float2 xv  = *(const float2*)&x[(size_t)t * (NN * 2) + grow * 2];
        *(uint2*)&su[tid * SUP0 + 128] = f4_to_b4(make_float4(axv.x, axv.y, xv.x, xv.y));
    }
    if (tid < 448) {
        int r = tid >> 4, lane = tid & 15;
        int grow = min(row0 + r, NN - 1);
        int len = g_len[grow];
        const int2* cb = g_cv + (size_t)grow * MAXW;
        float4 a4 = make_float4(0.f, 0.f, 0.f, 0.f);
        #pragma unroll 4
        for (int k = 0; k < len; k++) {
            int2 cv = __ldg(&cb[k]);
            gacc(a4, __int_as_float(cv.y), bin, cv.x, lane);
        }
        *(uint2*)&su[r * SUP0 + lane * 4] = f4_to_b4(a4);
    }
    __syncthreads();

    {
        const int w = tid >> 5, tl = tid & 31;
        const int mt = w & 1, nc = w >> 1;
        const int rA = mt * 16 + (tl >> 2);
        const int cA = 2 * (tl & 3);
        float c[4][4];
        #pragma unroll
        for (int j = 0; j < 4; j++) { c[j][0] = c[j][1] = c[j][2] = c[j][3] = 0.f; }
        #pragma unroll 1
        for (int kt = 0; kt < NKT0; kt++) {
            unsigned a0 = *(const unsigned*)&su[rA * SUP0 + kt * 16 + cA];
            unsigned a1 = *(const unsigned*)&su[(rA + 8) * SUP0 + kt * 16 + cA];
            unsigned a2 = *(const unsigned*)&su[rA * SUP0 + kt * 16 + cA + 8];
            unsigned a3 = *(const unsigned*)&su[(rA + 8) * SUP0 + kt * 16 + cA + 8];
            #pragma unroll
            for (int j = 0; j < 4; j++) {
                int nt = nc * 4 + j;
                uint2 b = __ldg((const uint2*)g_Wp0 + (nt * NKT0 + kt) * 32 + tl);
                mma_bf16(c[j], a0, a1, a2, a3, b.x, b.y);
            }
        }
        int r = mt * 16 + (tl >> 2);
        #pragma unroll
        for (int j = 0; j < 4; j++) {
            int n = nc * 32 + j * 8 + 2 * (tl & 3);
            float2 bb = *(const float2*)&g_b0[n];
            cw[r * CWP + n]           = c[j][0] + bb.x;
            cw[r * CWP + n + 1]       = c[j][1] + bb.y;
            cw[(r + 8) * CWP + n]     = c[j][2] + bb.x;
            cw[(r + 8) * CWP + n + 1] = c[j][3] + bb.y;
        }
    }
    __syncthreads();

    const float* __restrict__ cold = g_c0[pin];
    float* __restrict__ cn = g_c0[pout];
    __nv_bfloat16* __restrict__ bo = g_bh0[pout];
    for (int i = tid; i < ROWS * HH; i += NTHR0) {
        int r = i >> 6, h = i & 63;
        int grow = row0 + r;
        if (grow < NN) {
            float ig = cw[r * CWP + h],       fg = cw[r * CWP + 64 + h];
            float og = cw[r * CWP + 128 + h], gg = cw[r * CWP + 192 + h];
            size_t gi = (size_t)grow * HH + h;
            float cvv = sigf(fg) * cold[gi] + sigf(ig) * tanhf2(gg);
            cn[gi] = cvv;
            bo[gi] = __float2bfloat16(sigf(og) * tanhf2(cvv));
        }
    }
}

// ================= fused step: cell1(t) + cell0(t+1) =================
// smem: su1 bf16[32][SUP1] | su0 bf16[32][SUP0] | cw1 f32[32][CWP] | cw0 f32[32][CWP]
#define O_SU0 (32 * SUP1 * 2)
#define O_CW1 (O_SU0 + 32 * SUP0 * 2)
#define O_CW0 (O_CW1 + 32 * CWP * 4)
#define STEP_SMEM (O_CW0 + 32 * CWP * 4)

__global__ __launch_bounds__(1024) void k_step(const float* __restrict__ x,
                                               const float* __restrict__ outW,
                                               const float* __restrict__ outb,
                                               float* __restrict__ out, int t) {
    extern __shared__ __align__(16) char smem[];
    __nv_bfloat16* su1 = (__nv_bfloat16*)smem;
    __nv_bfloat16* su0 = (__nv_bfloat16*)(smem + O_SU0);
    float* cw1 = (float*)(smem + O_CW1);
    float* cw0 = (float*)(smem + O_CW0);
    float* hl  = (float*)(smem + O_SU0);      // aliases su0 (last step only)

    const int tid  = threadIdx.x;
    const int row0 = blockIdx.x * ROWS;
    const int pin = t & 1, pout = pin ^ 1;
    const bool last = (t == TT - 1);
    const __nv_bfloat16* __restrict__ bh0n = g_bh0[pout];   // new h0 (from prev launch)
    const __nv_bfloat16* __restrict__ bh1o = g_bh1[pin];    // old h1

    // zero su1 + su0
    {
        uint4* p = (uint4*)smem;
        for (int i = tid; i < (32 * SUP1 + 32 * SUP0) / 8; i += 1024) p[i] = make_uint4(0, 0, 0, 0);
    }
    __syncthreads();

    // direct operands
    if (tid < 448) {
        int r = tid >> 4, lane = tid & 15;
        int grow = min(row0 + r, NN - 1);
        uint2 v0 = *((const uint2*)(bh0n + (size_t)grow * HH) + lane);
        uint2 v1 = *((const uint2*)(bh1o + (size_t)grow * HH) + lane);
        *(uint2*)&su1[r * SUP1 + 64 + lane * 4]  = v0;
        *(uint2*)&su1[r * SUP1 + 192 + lane * 4] = v1;
        *(uint2*)&su0[r * SUP0 + 64 + lane * 4]  = v0;
    }
    if (tid < ROWS && !last) {
        int grow = min(row0 + tid, NN - 1);
        float2 axv = *(const float2*)&g_AX[((size_t)(t + 1) * NN + grow) * 2];
        float2 xv  = *(const float2*)&x[(size_t)(t + 1) * (NN * 2) + grow * 2];
        *(uint2*)&su0[tid * SUP0 + 128] = f4_to_b4(make_float4(axv.x, axv.y, xv.x, xv.y));
    }
    // shared gather: a0 = A@h0n (used by BOTH cells), a1 = A@h1o; split-k over 2 halves
    if (tid < 896) {
        int r = tid >> 5, half = (tid >> 4) & 1, lane = tid & 15;
        int grow = min(row0 + r, NN - 1);
        int len = g_len[grow];
        const int2* cb = g_cv + (size_t)grow * MAXW;
        float4 a0 = make_float4(0.f, 0.f, 0.f, 0.f);
        float4 a1 = make_float4(0.f, 0.f, 0.f, 0.f);
        #pragma unroll 2
        for (int k = half; k < len; k += 2) {
            int2 cv = __ldg(&cb[k]);
            float v = __int_as_float(cv.y);
            gacc(a0, v, bh0n, cv.x, lane);
            gacc(a1, v, bh1o, cv.x, lane);
        }
        a0.x += __shfl_xor_sync(0xffffffffu, a0.x, 16);
        a0.y += __shfl_xor_sync(0xffffffffu, a0.y, 16);
        a0.z += __shfl_xor_sync(0xffffffffu, a0.z, 16);
        a0.w += __shfl_xor_sync(0xffffffffu, a0.w, 16);
        a1.x += __shfl_xor_sync(0xffffffffu, a1.x, 16);
        a1.y += __shfl_xor_sync(0xffffffffu, a1.y, 16);
        a1.z += __shfl_xor_sync(0xffffffffu, a1.z, 16);
        a1.w += __shfl_xor_sync(0xffffffffu, a1.w, 16);
        if (half == 0) {
            uint2 p0 = f4_to_b4(a0), p1 = f4_to_b4(a1);
            *(uint2*)&su1[r * SUP1 + lane * 4]       = p0;
            *(uint2*)&su0[r * SUP0 + lane * 4]       = p0;
            *(uint2*)&su1[r * SUP1 + 128 + lane * 4] = p1;
        }
    }
    __syncthreads();

    // MMA: 32 warps = 2 m-tiles x 16 n-quads(16 cols)
    const int w = tid >> 5, tl = tid & 31;
    const int mt = w & 1, nq = w >> 1;
    const int rA = mt * 16 + (tl >> 2), cA = 2 * (tl & 3);
    float c1r[2][4], c0r[2][4];
    #pragma unroll
    for (int j = 0; j < 2; j++)
        #pragma unroll
        for (int q = 0; q < 4; q++) { c1r[j][q] = 0.f; c0r[j][q] = 0.f; }
    {   // cell1: K = 256, pipelined B loads
        const uint2* p0 = (const uint2*)g_Wp1 + ((nq * 2)     * NKT1) * 32 + tl;
        const uint2* p1 = (const uint2*)g_Wp1 + ((nq * 2 + 1) * NKT1) * 32 + tl;
        uint2 b0 = __ldg(p0), b1 = __ldg(p1);
        #pragma unroll 1
        for (int kt = 0; kt < NKT1; kt++) {
            uint2 n0, n1;
            if (kt < NKT1 - 1) { n0 = __ldg(p0 + (kt + 1) * 32); n1 = __ldg(p1 + (kt + 1) * 32); }
            unsigned a0 = *(const unsigned*)&su1[rA * SUP1 + kt * 16 + cA];
            unsigned a1 = *(const unsigned*)&su1[(rA + 8) * SUP1 + kt * 16 + cA];
            unsigned a2 = *(const unsigned*)&su1[rA * SUP1 + kt * 16 + cA + 8];
            unsigned a3 = *(const unsigned*)&su1[(rA + 8) * SUP1 + kt * 16 + cA + 8];
            mma_bf16(c1r[0], a0, a1, a2, a3, b0.x, b0.y);
            mma_bf16(c1r[1], a0, a1, a2, a3, b1.x, b1.y);
            b0 = n0; b1 = n1;
        }
    }
    if (!last) {   // cell0(t+1): K = 144, pipelined
        const uint2* p0 = (const uint2*)g_Wp0 + ((nq * 2)     * NKT0) * 32 + tl;
        const uint2* p1 = (const uint2*)g_Wp0 + ((nq * 2 + 1) * NKT0) * 32 + tl;
        uint2 b0 = __ldg(p0), b1 = __ldg(p1);
        #pragma unroll 1
        for (int kt = 0; kt < NKT0; kt++) {
            uint2 n0, n1;
            if (kt < NKT0 - 1) { n0 = __ldg(p0 + (kt + 1) * 32); n1 = __ldg(p1 + (kt + 1) * 32); }
            unsigned a0 = *(const unsigned*)&su0[rA * SUP0 + kt * 16 + cA];
            unsigned a1 = *(const unsigned*)&su0[(rA + 8) * SUP0 + kt * 16 + cA];
            unsigned a2 = *(const unsigned*)&su0[rA * SUP0 + kt * 16 + cA + 8];
            unsigned a3 = *(const unsigned*)&su0[(rA + 8) * SUP0 + kt * 16 + cA + 8];
            mma_bf16(c0r[0], a0, a1, a2, a3, b0.x, b0.y);
            mma_bf16(c0r[1], a0, a1, a2, a3, b1.x, b1.y);
            b0 = n0; b1 = n1;
        }
    }
    {   // write combs (+bias)
        int r = mt * 16 + (tl >> 2);
        #pragma unroll
        for (int j = 0; j < 2; j++) {
            int n = nq * 16 + j * 8 + 2 * (tl & 3);
            float2 bb1 = *(const float2*)&g_b1[n];
            cw1[r * CWP + n]           = c1r[j][0] + bb1.x;
            cw1[r * CWP + n + 1]       = c1r[j][1] + bb1.y;
            cw1[(r + 8) * CWP + n]     = c1r[j][2] + bb1.x;
            cw1[(r + 8) * CWP + n + 1] = c1r[j][3] + bb1.y;
            if (!last) {
                float2 bb0 = *(const float2*)&g_b0[n];
                cw0[r * CWP + n]           = c0r[j][0] + bb0.x;
                cw0[r * CWP + n + 1]       = c0r[j][1] + bb0.y;
                cw0[(r + 8) * CWP + n]     = c0r[j][2] + bb0.x;
                cw0[(r + 8) * CWP + n + 1] = c0r[j][3] + bb0.y;
            }
        }
    }
    __syncthreads();

    // epilogue cell1(t)
    {
        const float* __restrict__ cold = g_c1[pin];
        float* __restrict__ cn = g_c1[pout];
        __nv_bfloat16* __restrict__ bo = g_bh1[pout];
        #pragma unroll
        for (int it = 0; it < 2; it++) {
            int i = tid + it * 1024;
            if (i < ROWS * HH) {
                int r = i >> 6, h = i & 63;
                int grow = row0 + r;
                if (grow < NN) {
                    float ig = cw1[r * CWP + h],       fg = cw1[r * CWP + 64 + h];
                    float og = cw1[r * CWP + 128 + h], gg = cw1[r * CWP + 192 + h];
                    size_t gi = (size_t)grow * HH + h;
                    float cvv = sigf(fg) * cold[gi] + sigf(ig) * tanhf2(gg);
                    cn[gi] = cvv;
                    float hv = sigf(og) * tanhf2(cvv);
                    bo[gi] = __float2bfloat16(hv);
                    if (last) hl[r * 64 + h] = hv;
                }
            }
        }
    }
    if (!last) {
        // epilogue cell0(t+1): pin' = pout, pout' = pin
        const float* __restrict__ cold = g_c0[pout];
        float* __restrict__ cn = g_c0[pin];
        __nv_bfloat16* __restrict__ bo = g_bh0[pin];
        #pragma unroll
        for (int it = 0; it < 2; it++) {
            int i = tid + it * 1024;
            if (i < ROWS * HH) {
                int r = i >> 6, h = i & 63;
                int grow = row0 + r;
                if (grow < NN) {
                    float ig = cw0[r * CWP + h],       fg = cw0[r * CWP + 64 + h];
                    float og = cw0[r * CWP + 128 + h], gg = cw0[r * CWP + 192 + h];
                    size_t gi = (size_t)grow * HH + h;
                    float cvv = sigf(fg) * cold[gi] + sigf(ig) * tanhf2(gg);
                    cn[gi] = cvv;
                    bo[gi] = __float2bfloat16(sigf(og) * tanhf2(cvv));
                }
            }
        }
    } else {
        // output projection from fp32 h1 in smem
        __syncthreads();
        if (tid < ROWS * 12) {
            int r = tid / 12, p = tid - r * 12;
            int grow = row0 + r;
            if (grow < NN) {
                float s = outb[p];
                #pragma unroll
                for (int k = 0; k < HH; k++) s += hl[r * 64 + k] * outW[k * 12 + p];
                out[grow * 12 + p] = s;
            }
        }
    }
}

extern "C" void kernel_launch(void* const* d_in, const int* in_sizes, int n_in,
                              void* d_out, int out_size) {
    const float* x     = (const float*)d_in[0];
    const float* adj   = (const float*)d_in[1];
    const float* gcWi0 = (const float*)d_in[2];
    const float* gcbi0 = (const float*)d_in[3];
    const float* gcWh0 = (const float*)d_in[4];
    const float* gcbh0 = (const float*)d_in[5];
    const float* liWi0 = (const float*)d_in[6];
    const float* libi0 = (const float*)d_in[7];
    const float* liWh0 = (const float*)d_in[8];
    const float* libh0 = (const float*)d_in[9];
    const float* gcWi1 = (const float*)d_in[10];
    const float* gcbi1 = (const float*)d_in[11];
    const float* gcWh1 = (const float*)d_in[12];
    const float* gcbh1 = (const float*)d_in[13];
    const float* liWi1 = (const float*)d_in[14];
    const float* libi1 = (const float*)d_in[15];
    const float* liWh1 = (const float*)d_in[16];
    const float* libh1 = (const float*)d_in[17];
    const float* outW  = (const float*)d_in[18];
    const float* outb  = (const float*)d_in[19];
    float* out = (float*)d_out;

    cudaFuncSetAttribute(k_cell0, cudaFuncAttributeMaxDynamicSharedMemorySize, C0_SMEM);
    cudaFuncSetAttribute(k_step, cudaFuncAttributeMaxDynamicSharedMemorySize, STEP_SMEM);

    k_dinv<<<NN / 8, 256>>>(adj);
    k_build<<<NN / 8, 256>>>(adj);
    k_prep<<<(PREP_TOTAL + 255) / 256, 256>>>(x,
        gcWi0, gcWh0, liWi0, liWh0, gcWi1, liWi1, gcWh1, liWh1,
        gcbi0, gcbh0, libi0, libh0, gcbi1, gcbh1, libi1, libh1);

    k_cell0<<<GRID, NTHR0, C0_SMEM>>>(x, 0, 0, 1);           // cell0 of step 0
    for (int t = 0; t < TT; t++)
        k_step<<<GRID, 1024, STEP_SMEM>>>(x, outW, outb, out, t);  // cell1(t) + cell0(t+1)
}